// round 1
// baseline (speedup 1.0000x reference)
#include <cuda_runtime.h>
#include <math.h>

// ---------------------------------------------------------------------------
// SimpleAttention: y = softmax((XWq+bq)(XWk+bk)^T / sqrt(h)) (XWv+bv) Wh + bh
// b=4, s=2048, h=1024, out=1024.  All fp32 SIMT baseline.
// ---------------------------------------------------------------------------

#define BATCH 4
#define SEQ   2048
#define HID   1024
#define OUTD  1024
#define ROWS  (BATCH * SEQ)          // 8192

// Scratch: Q, K, V, Ctx (each ROWS*HID) + S (BATCH*SEQ*SEQ)
// 4*8M + 16M = 48M floats = 192 MB static device scratch (no allocations).
__device__ float g_scratch[4ull * ROWS * HID + (unsigned long long)BATCH * SEQ * SEQ];

#define BM 128
#define BN 128
#define BKK 8
#define TM 8
#define TN 8

// C[M,N] = A[M,K] @ B[K,N] (+ bias), batched via blockIdx.z with strides.
__global__ __launch_bounds__(256, 2)
void gemm_nn_bias(const float* __restrict__ A, const float* __restrict__ B,
                  const float* __restrict__ bias, float* __restrict__ C,
                  int M, int N, int K,
                  long long sA, long long sB, long long sC)
{
    A += (long long)blockIdx.z * sA;
    B += (long long)blockIdx.z * sB;
    C += (long long)blockIdx.z * sC;

    __shared__ float As[BKK][BM];
    __shared__ float Bs[BKK][BN];

    const int tid = threadIdx.x;                 // 0..255
    const int m0 = blockIdx.y * BM;
    const int n0 = blockIdx.x * BN;
    const int tx = tid & 15;                     // 0..15
    const int ty = tid >> 4;                     // 0..15

    // A-tile load: 128 rows x 8 cols, float4 per thread (2 threads/row)
    const int arow = tid >> 1;
    const int acol = (tid & 1) * 4;
    // B-tile load: 8 rows x 128 cols, float4 per thread (32 threads/row)
    const int brow = tid >> 5;
    const int bcol = (tid & 31) * 4;

    const float* Aptr = A + (long long)(m0 + arow) * K + acol;
    const float* Bptr = B + (long long)brow * N + (n0 + bcol);

    float acc[TM][TN];
    #pragma unroll
    for (int i = 0; i < TM; ++i)
        #pragma unroll
        for (int j = 0; j < TN; ++j) acc[i][j] = 0.f;

    for (int k0 = 0; k0 < K; k0 += BKK) {
        float4 av = *(const float4*)(Aptr + k0);
        As[acol + 0][arow] = av.x;
        As[acol + 1][arow] = av.y;
        As[acol + 2][arow] = av.z;
        As[acol + 3][arow] = av.w;
        *(float4*)&Bs[brow][bcol] = *(const float4*)(Bptr + (long long)k0 * N);
        __syncthreads();

        #pragma unroll
        for (int k = 0; k < BKK; ++k) {
            float4 a0 = *(const float4*)&As[k][ty * TM];
            float4 a1 = *(const float4*)&As[k][ty * TM + 4];
            float4 b0 = *(const float4*)&Bs[k][tx * TN];
            float4 b1 = *(const float4*)&Bs[k][tx * TN + 4];
            float a[TM] = {a0.x, a0.y, a0.z, a0.w, a1.x, a1.y, a1.z, a1.w};
            float b[TN] = {b0.x, b0.y, b0.z, b0.w, b1.x, b1.y, b1.z, b1.w};
            #pragma unroll
            for (int i = 0; i < TM; ++i)
                #pragma unroll
                for (int j = 0; j < TN; ++j)
                    acc[i][j] = fmaf(a[i], b[j], acc[i][j]);
        }
        __syncthreads();
    }

    #pragma unroll
    for (int i = 0; i < TM; ++i) {
        const int r = m0 + ty * TM + i;
        #pragma unroll
        for (int j = 0; j < TN; ++j) {
            const int c = n0 + tx * TN + j;
            float v = acc[i][j];
            if (bias) v += bias[c];
            C[(long long)r * N + c] = v;
        }
    }
}

// C[M,N] = alpha * A[M,K] @ B[N,K]^T, batched via blockIdx.z.
__global__ __launch_bounds__(256, 2)
void gemm_nt_scaled(const float* __restrict__ A, const float* __restrict__ B,
                    float* __restrict__ C,
                    int M, int N, int K, float alpha,
                    long long sA, long long sB, long long sC)
{
    A += (long long)blockIdx.z * sA;
    B += (long long)blockIdx.z * sB;
    C += (long long)blockIdx.z * sC;

    __shared__ float As[BKK][BM];
    __shared__ float Bs[BKK][BN];

    const int tid = threadIdx.x;
    const int m0 = blockIdx.y * BM;
    const int n0 = blockIdx.x * BN;
    const int tx = tid & 15;
    const int ty = tid >> 4;

    const int lrow = tid >> 1;          // 0..127
    const int lcol = (tid & 1) * 4;     // 0 or 4

    const float* Aptr = A + (long long)(m0 + lrow) * K + lcol;
    const float* Bptr = B + (long long)(n0 + lrow) * K + lcol;

    float acc[TM][TN];
    #pragma unroll
    for (int i = 0; i < TM; ++i)
        #pragma unroll
        for (int j = 0; j < TN; ++j) acc[i][j] = 0.f;

    for (int k0 = 0; k0 < K; k0 += BKK) {
        float4 av = *(const float4*)(Aptr + k0);
        float4 bv = *(const float4*)(Bptr + k0);
        As[lcol + 0][lrow] = av.x;
        As[lcol + 1][lrow] = av.y;
        As[lcol + 2][lrow] = av.z;
        As[lcol + 3][lrow] = av.w;
        Bs[lcol + 0][lrow] = bv.x;
        Bs[lcol + 1][lrow] = bv.y;
        Bs[lcol + 2][lrow] = bv.z;
        Bs[lcol + 3][lrow] = bv.w;
        __syncthreads();

        #pragma unroll
        for (int k = 0; k < BKK; ++k) {
            float4 a0 = *(const float4*)&As[k][ty * TM];
            float4 a1 = *(const float4*)&As[k][ty * TM + 4];
            float4 b0 = *(const float4*)&Bs[k][tx * TN];
            float4 b1 = *(const float4*)&Bs[k][tx * TN + 4];
            float a[TM] = {a0.x, a0.y, a0.z, a0.w, a1.x, a1.y, a1.z, a1.w};
            float b[TN] = {b0.x, b0.y, b0.z, b0.w, b1.x, b1.y, b1.z, b1.w};
            #pragma unroll
            for (int i = 0; i < TM; ++i)
                #pragma unroll
                for (int j = 0; j < TN; ++j)
                    acc[i][j] = fmaf(a[i], b[j], acc[i][j]);
        }
        __syncthreads();
    }

    #pragma unroll
    for (int i = 0; i < TM; ++i) {
        const int r = m0 + ty * TM + i;
        #pragma unroll
        for (int j = 0; j < TN; ++j) {
            const int c = n0 + tx * TN + j;
            C[(long long)r * N + c] = acc[i][j] * alpha;
        }
    }
}

// In-place row softmax: one block (256 threads) per row of length N.
__global__ __launch_bounds__(256)
void softmax_rows(float* __restrict__ S, int N)
{
    float* row = S + (long long)blockIdx.x * N;
    const int tid = threadIdx.x;
    __shared__ float red[256];

    float vmax = -INFINITY;
    for (int i = tid; i < N; i += 256) vmax = fmaxf(vmax, row[i]);
    red[tid] = vmax;
    __syncthreads();
    #pragma unroll
    for (int s = 128; s > 0; s >>= 1) {
        if (tid < s) red[tid] = fmaxf(red[tid], red[tid + s]);
        __syncthreads();
    }
    vmax = red[0];
    __syncthreads();

    float sum = 0.f;
    for (int i = tid; i < N; i += 256) {
        float e = __expf(row[i] - vmax);
        row[i] = e;
        sum += e;
    }
    red[tid] = sum;
    __syncthreads();
    #pragma unroll
    for (int s = 128; s > 0; s >>= 1) {
        if (tid < s) red[tid] += red[tid + s];
        __syncthreads();
    }
    const float inv = 1.f / red[0];
    __syncthreads();

    for (int i = tid; i < N; i += 256) row[i] *= inv;
}

extern "C" void kernel_launch(void* const* d_in, const int* in_sizes, int n_in,
                              void* d_out, int out_size)
{
    const float* X  = (const float*)d_in[0];
    const float* Wq = (const float*)d_in[1];
    const float* bq = (const float*)d_in[2];
    const float* Wk = (const float*)d_in[3];
    const float* bk = (const float*)d_in[4];
    const float* Wv = (const float*)d_in[5];
    const float* bv = (const float*)d_in[6];
    const float* Wh = (const float*)d_in[7];
    const float* bh = (const float*)d_in[8];
    float* out = (float*)d_out;

    float* base = nullptr;
    cudaGetSymbolAddress((void**)&base, g_scratch);
    float* Q   = base;
    float* K   = Q + (long long)ROWS * HID;
    float* V   = K + (long long)ROWS * HID;
    float* Ctx = V + (long long)ROWS * HID;
    float* S   = Ctx + (long long)ROWS * HID;

    const float scale = 1.0f / 32.0f;  // 1/sqrt(1024)

    // Q/K/V projections: [8192,1024] @ [1024,1024] + bias
    {
        dim3 grid(HID / BN, ROWS / BM, 1);
        gemm_nn_bias<<<grid, 256>>>(X, Wq, bq, Q, ROWS, HID, HID, 0, 0, 0);
        gemm_nn_bias<<<grid, 256>>>(X, Wk, bk, K, ROWS, HID, HID, 0, 0, 0);
        gemm_nn_bias<<<grid, 256>>>(X, Wv, bv, V, ROWS, HID, HID, 0, 0, 0);
    }

    // scores = scale * Q @ K^T, batched
    {
        dim3 grid(SEQ / BN, SEQ / BM, BATCH);
        gemm_nt_scaled<<<grid, 256>>>(Q, K, S, SEQ, SEQ, HID, scale,
                                      (long long)SEQ * HID,
                                      (long long)SEQ * HID,
                                      (long long)SEQ * SEQ);
    }

    // softmax rows
    softmax_rows<<<BATCH * SEQ, 256>>>(S, SEQ);

    // context = attn @ V, batched
    {
        dim3 grid(HID / BN, SEQ / BM, BATCH);
        gemm_nn_bias<<<grid, 256>>>(S, V, nullptr, Ctx, SEQ, HID, SEQ,
                                    (long long)SEQ * SEQ,
                                    (long long)SEQ * HID,
                                    (long long)SEQ * HID);
    }

    // y = context @ Wh + bh
    {
        dim3 grid(OUTD / BN, ROWS / BM, 1);
        gemm_nn_bias<<<grid, 256>>>(Ctx, Wh, bh, out, ROWS, OUTD, HID, 0, 0, 0);
    }
}

// round 2
// speedup vs baseline: 3.6345x; 3.6345x over previous
#include <cuda_runtime.h>
#include <math.h>
#include <stdint.h>

// ---------------------------------------------------------------------------
// SimpleAttention via tf32 tensor-core GEMMs (mma.sync m16n8k8) + cp.async.
// b=4, s=2048, h=1024, out=1024.
// ---------------------------------------------------------------------------

#define BATCH 4
#define SEQ   2048
#define HID   1024
#define OUTD  1024
#define ROWS  (BATCH * SEQ)          // 8192

__device__ float g_scratch[4ull * ROWS * HID + (unsigned long long)BATCH * SEQ * SEQ];

// ----------------------------- PTX helpers --------------------------------
__device__ __forceinline__ void cp_async16(void* smem, const void* gmem) {
    uint32_t s = (uint32_t)__cvta_generic_to_shared(smem);
    asm volatile("cp.async.cg.shared.global [%0], [%1], 16;\n" :: "r"(s), "l"(gmem));
}
__device__ __forceinline__ void cp_commit() { asm volatile("cp.async.commit_group;\n"); }
__device__ __forceinline__ void cp_wait1()  { asm volatile("cp.async.wait_group 1;\n"); }
__device__ __forceinline__ void cp_wait0()  { asm volatile("cp.async.wait_group 0;\n"); }

__device__ __forceinline__ uint32_t f2tf(float x) {
    uint32_t r;
    asm("cvt.rna.tf32.f32 %0, %1;\n" : "=r"(r) : "f"(x));
    return r;
}

__device__ __forceinline__ void mma_tf32(float* d, const uint32_t* a, const uint32_t* b) {
    asm volatile(
        "mma.sync.aligned.m16n8k8.row.col.f32.tf32.tf32.f32 "
        "{%0,%1,%2,%3}, {%4,%5,%6,%7}, {%8,%9}, {%0,%1,%2,%3};\n"
        : "+f"(d[0]), "+f"(d[1]), "+f"(d[2]), "+f"(d[3])
        : "r"(a[0]), "r"(a[1]), "r"(a[2]), "r"(a[3]), "r"(b[0]), "r"(b[1]));
}

// Tile geometry (shared by both GEMM kernels)
#define BM 128
#define BN 128
#define BK 32
#define APAD 4     // row stride 36 floats (144B, 16B aligned, conflict-free)
#define BPAD 8     // row stride 136 floats (544B, 16B aligned, conflict-free)
#define ASTR (BK + APAD)     // 36
#define BSTR (BN + BPAD)     // 136

#define A_TILE_F (BM * ASTR)            // 4608 floats per buffer
#define BN_TILE_F (BK * BSTR)           // 4352 floats per buffer (NN layout)
#define BT_TILE_F (BM * ASTR)           // 4608 floats per buffer (NT layout)

// ===========================================================================
// NN: C[M,N] = A[M,K] @ B[K,N] (+bias), batched via blockIdx.z.
// ===========================================================================
__global__ __launch_bounds__(256, 2)
void gemm_nn_tc(const float* __restrict__ A, const float* __restrict__ B,
                const float* __restrict__ bias, float* __restrict__ C,
                int M, int N, int K,
                long long sA, long long sB, long long sC)
{
    A += (long long)blockIdx.z * sA;
    B += (long long)blockIdx.z * sB;
    C += (long long)blockIdx.z * sC;

    extern __shared__ float smem[];
    float* As = smem;                       // [2][BM][ASTR]
    float* Bs = smem + 2 * A_TILE_F;        // [2][BK][BSTR]

    const int tid  = threadIdx.x;
    const int lane = tid & 31;
    const int warp = tid >> 5;
    const int wm = warp >> 2;               // 0..1  -> 64-row slab
    const int wn = warp & 3;                // 0..3  -> 32-col slab
    const int g  = lane >> 2;               // 0..7
    const int t4 = lane & 3;                // 0..3

    const int m0 = blockIdx.y * BM;
    const int n0 = blockIdx.x * BN;

    // loader indices
    const int lr = tid >> 3;                // 0..31
    const int lc = (tid & 7) * 4;           // 0,4,...,28

    const float* Ag = A + (long long)(m0 + lr) * K + lc;
    const float* Bg = B + (long long)lr * N + n0 + lc;

    float acc[4][4][4];
    #pragma unroll
    for (int i = 0; i < 4; ++i)
        #pragma unroll
        for (int j = 0; j < 4; ++j)
            #pragma unroll
            for (int q = 0; q < 4; ++q) acc[i][j][q] = 0.f;

    const int iters = K / BK;

    // prologue
    {
        float* ab = As;
        float* bb = Bs;
        #pragma unroll
        for (int p = 0; p < 4; ++p)
            cp_async16(&ab[(lr + p * 32) * ASTR + lc], Ag + (long long)p * 32 * K);
        #pragma unroll
        for (int p = 0; p < 4; ++p)
            cp_async16(&bb[lr * BSTR + lc + p * 32], Bg + p * 32);
        cp_commit();
    }

    for (int it = 0; it < iters; ++it) {
        const int buf = it & 1;
        if (it + 1 < iters) {
            const int k0n = (it + 1) * BK;
            float* ab = As + (buf ^ 1) * A_TILE_F;
            float* bb = Bs + (buf ^ 1) * BN_TILE_F;
            #pragma unroll
            for (int p = 0; p < 4; ++p)
                cp_async16(&ab[(lr + p * 32) * ASTR + lc],
                           Ag + (long long)p * 32 * K + k0n);
            #pragma unroll
            for (int p = 0; p < 4; ++p)
                cp_async16(&bb[lr * BSTR + lc + p * 32],
                           Bg + (long long)k0n * N + p * 32);
            cp_commit();
            cp_wait1();
        } else {
            cp_wait0();
        }
        __syncthreads();

        const float* ab = As + buf * A_TILE_F;
        const float* bb = Bs + buf * BN_TILE_F;

        #pragma unroll
        for (int kk = 0; kk < BK; kk += 8) {
            uint32_t af[4][4], bf[4][2];
            #pragma unroll
            for (int im = 0; im < 4; ++im) {
                const int m = wm * 64 + im * 16;
                af[im][0] = f2tf(ab[(m + g)     * ASTR + kk + t4]);
                af[im][1] = f2tf(ab[(m + g + 8) * ASTR + kk + t4]);
                af[im][2] = f2tf(ab[(m + g)     * ASTR + kk + t4 + 4]);
                af[im][3] = f2tf(ab[(m + g + 8) * ASTR + kk + t4 + 4]);
            }
            #pragma unroll
            for (int in = 0; in < 4; ++in) {
                const int n = wn * 32 + in * 8;
                bf[in][0] = f2tf(bb[(kk + t4)     * BSTR + n + g]);
                bf[in][1] = f2tf(bb[(kk + t4 + 4) * BSTR + n + g]);
            }
            #pragma unroll
            for (int im = 0; im < 4; ++im)
                #pragma unroll
                for (int in = 0; in < 4; ++in)
                    mma_tf32(acc[im][in], af[im], bf[in]);
        }
        __syncthreads();
    }

    // epilogue
    #pragma unroll
    for (int im = 0; im < 4; ++im) {
        const int r0 = m0 + wm * 64 + im * 16 + g;
        #pragma unroll
        for (int in = 0; in < 4; ++in) {
            const int c = n0 + wn * 32 + in * 8 + 2 * t4;
            float b0 = 0.f, b1 = 0.f;
            if (bias) { b0 = bias[c]; b1 = bias[c + 1]; }
            float2 v01 = make_float2(acc[im][in][0] + b0, acc[im][in][1] + b1);
            float2 v23 = make_float2(acc[im][in][2] + b0, acc[im][in][3] + b1);
            *(float2*)&C[(long long)r0 * N + c]       = v01;
            *(float2*)&C[(long long)(r0 + 8) * N + c] = v23;
        }
    }
}

// ===========================================================================
// NT: C[M,N] = alpha * A[M,K] @ B[N,K]^T, batched via blockIdx.z.
// ===========================================================================
__global__ __launch_bounds__(256, 2)
void gemm_nt_tc(const float* __restrict__ A, const float* __restrict__ B,
                float* __restrict__ C,
                int M, int N, int K, float alpha,
                long long sA, long long sB, long long sC)
{
    A += (long long)blockIdx.z * sA;
    B += (long long)blockIdx.z * sB;
    C += (long long)blockIdx.z * sC;

    extern __shared__ float smem[];
    float* As = smem;                       // [2][BM][ASTR]
    float* Bs = smem + 2 * A_TILE_F;        // [2][BN][ASTR] (row-major like A)

    const int tid  = threadIdx.x;
    const int lane = tid & 31;
    const int warp = tid >> 5;
    const int wm = warp >> 2;
    const int wn = warp & 3;
    const int g  = lane >> 2;
    const int t4 = lane & 3;

    const int m0 = blockIdx.y * BM;
    const int n0 = blockIdx.x * BN;

    const int lr = tid >> 3;
    const int lc = (tid & 7) * 4;

    const float* Ag = A + (long long)(m0 + lr) * K + lc;
    const float* Bg = B + (long long)(n0 + lr) * K + lc;

    float acc[4][4][4];
    #pragma unroll
    for (int i = 0; i < 4; ++i)
        #pragma unroll
        for (int j = 0; j < 4; ++j)
            #pragma unroll
            for (int q = 0; q < 4; ++q) acc[i][j][q] = 0.f;

    const int iters = K / BK;

    {
        float* ab = As;
        float* bb = Bs;
        #pragma unroll
        for (int p = 0; p < 4; ++p)
            cp_async16(&ab[(lr + p * 32) * ASTR + lc], Ag + (long long)p * 32 * K);
        #pragma unroll
        for (int p = 0; p < 4; ++p)
            cp_async16(&bb[(lr + p * 32) * ASTR + lc], Bg + (long long)p * 32 * K);
        cp_commit();
    }

    for (int it = 0; it < iters; ++it) {
        const int buf = it & 1;
        if (it + 1 < iters) {
            const int k0n = (it + 1) * BK;
            float* ab = As + (buf ^ 1) * A_TILE_F;
            float* bb = Bs + (buf ^ 1) * BT_TILE_F;
            #pragma unroll
            for (int p = 0; p < 4; ++p)
                cp_async16(&ab[(lr + p * 32) * ASTR + lc],
                           Ag + (long long)p * 32 * K + k0n);
            #pragma unroll
            for (int p = 0; p < 4; ++p)
                cp_async16(&bb[(lr + p * 32) * ASTR + lc],
                           Bg + (long long)p * 32 * K + k0n);
            cp_commit();
            cp_wait1();
        } else {
            cp_wait0();
        }
        __syncthreads();

        const float* ab = As + buf * A_TILE_F;
        const float* bb = Bs + buf * BT_TILE_F;

        #pragma unroll
        for (int kk = 0; kk < BK; kk += 8) {
            uint32_t af[4][4], bf[4][2];
            #pragma unroll
            for (int im = 0; im < 4; ++im) {
                const int m = wm * 64 + im * 16;
                af[im][0] = f2tf(ab[(m + g)     * ASTR + kk + t4]);
                af[im][1] = f2tf(ab[(m + g + 8) * ASTR + kk + t4]);
                af[im][2] = f2tf(ab[(m + g)     * ASTR + kk + t4 + 4]);
                af[im][3] = f2tf(ab[(m + g + 8) * ASTR + kk + t4 + 4]);
            }
            #pragma unroll
            for (int in = 0; in < 4; ++in) {
                const int n = wn * 32 + in * 8;
                bf[in][0] = f2tf(bb[(n + g) * ASTR + kk + t4]);
                bf[in][1] = f2tf(bb[(n + g) * ASTR + kk + t4 + 4]);
            }
            #pragma unroll
            for (int im = 0; im < 4; ++im)
                #pragma unroll
                for (int in = 0; in < 4; ++in)
                    mma_tf32(acc[im][in], af[im], bf[in]);
        }
        __syncthreads();
    }

    #pragma unroll
    for (int im = 0; im < 4; ++im) {
        const int r0 = m0 + wm * 64 + im * 16 + g;
        #pragma unroll
        for (int in = 0; in < 4; ++in) {
            const int c = n0 + wn * 32 + in * 8 + 2 * t4;
            float2 v01 = make_float2(acc[im][in][0] * alpha, acc[im][in][1] * alpha);
            float2 v23 = make_float2(acc[im][in][2] * alpha, acc[im][in][3] * alpha);
            *(float2*)&C[(long long)r0 * N + c]       = v01;
            *(float2*)&C[(long long)(r0 + 8) * N + c] = v23;
        }
    }
}

// ===========================================================================
// Row softmax, one block per row.
// ===========================================================================
__global__ __launch_bounds__(256)
void softmax_rows(float* __restrict__ S, int N)
{
    float* row = S + (long long)blockIdx.x * N;
    const int tid = threadIdx.x;
    __shared__ float red[256];

    float vmax = -INFINITY;
    for (int i = tid; i < N; i += 256) vmax = fmaxf(vmax, row[i]);
    red[tid] = vmax;
    __syncthreads();
    #pragma unroll
    for (int s = 128; s > 0; s >>= 1) {
        if (tid < s) red[tid] = fmaxf(red[tid], red[tid + s]);
        __syncthreads();
    }
    vmax = red[0];
    __syncthreads();

    float sum = 0.f;
    for (int i = tid; i < N; i += 256) {
        float e = __expf(row[i] - vmax);
        row[i] = e;
        sum += e;
    }
    red[tid] = sum;
    __syncthreads();
    #pragma unroll
    for (int s = 128; s > 0; s >>= 1) {
        if (tid < s) red[tid] += red[tid + s];
        __syncthreads();
    }
    const float inv = 1.f / red[0];
    __syncthreads();

    for (int i = tid; i < N; i += 256) row[i] *= inv;
}

// ===========================================================================
extern "C" void kernel_launch(void* const* d_in, const int* in_sizes, int n_in,
                              void* d_out, int out_size)
{
    const float* X  = (const float*)d_in[0];
    const float* Wq = (const float*)d_in[1];
    const float* bq = (const float*)d_in[2];
    const float* Wk = (const float*)d_in[3];
    const float* bk = (const float*)d_in[4];
    const float* Wv = (const float*)d_in[5];
    const float* bv = (const float*)d_in[6];
    const float* Wh = (const float*)d_in[7];
    const float* bh = (const float*)d_in[8];
    float* out = (float*)d_out;

    float* base = nullptr;
    cudaGetSymbolAddress((void**)&base, g_scratch);
    float* Q   = base;
    float* K   = Q + (long long)ROWS * HID;
    float* V   = K + (long long)ROWS * HID;
    float* Ctx = V + (long long)ROWS * HID;
    float* S   = Ctx + (long long)ROWS * HID;

    const float scale = 1.0f / 32.0f;  // 1/sqrt(1024)

    const int smem_nn = (2 * A_TILE_F + 2 * BN_TILE_F) * (int)sizeof(float);  // 71680
    const int smem_nt = (2 * A_TILE_F + 2 * BT_TILE_F) * (int)sizeof(float);  // 73728

    static bool attr_done = false;
    if (!attr_done) {
        cudaFuncSetAttribute(gemm_nn_tc, cudaFuncAttributeMaxDynamicSharedMemorySize, smem_nn);
        cudaFuncSetAttribute(gemm_nt_tc, cudaFuncAttributeMaxDynamicSharedMemorySize, smem_nt);
        attr_done = true;
    }

    // Q/K/V projections
    {
        dim3 grid(HID / BN, ROWS / BM, 1);
        gemm_nn_tc<<<grid, 256, smem_nn>>>(X, Wq, bq, Q, ROWS, HID, HID, 0, 0, 0);
        gemm_nn_tc<<<grid, 256, smem_nn>>>(X, Wk, bk, K, ROWS, HID, HID, 0, 0, 0);
        gemm_nn_tc<<<grid, 256, smem_nn>>>(X, Wv, bv, V, ROWS, HID, HID, 0, 0, 0);
    }

    // scores = scale * Q @ K^T (batched)
    {
        dim3 grid(SEQ / BN, SEQ / BM, BATCH);
        gemm_nt_tc<<<grid, 256, smem_nt>>>(Q, K, S, SEQ, SEQ, HID, scale,
                                           (long long)SEQ * HID,
                                           (long long)SEQ * HID,
                                           (long long)SEQ * SEQ);
    }

    softmax_rows<<<BATCH * SEQ, 256>>>(S, SEQ);

    // context = attn @ V (batched)
    {
        dim3 grid(HID / BN, SEQ / BM, BATCH);
        gemm_nn_tc<<<grid, 256, smem_nn>>>(S, V, nullptr, Ctx, SEQ, HID, SEQ,
                                           (long long)SEQ * SEQ,
                                           (long long)SEQ * HID,
                                           (long long)SEQ * HID);
    }

    // y = context @ Wh + bh
    {
        dim3 grid(OUTD / BN, ROWS / BM, 1);
        gemm_nn_tc<<<grid, 256, smem_nn>>>(Ctx, Wh, bh, out, ROWS, OUTD, HID, 0, 0, 0);
    }
}

// round 4
// speedup vs baseline: 3.8546x; 1.0606x over previous
#include <cuda_runtime.h>
#include <math.h>
#include <stdint.h>

// ---------------------------------------------------------------------------
// SimpleAttention via tf32 tensor-core GEMMs (mma.sync m16n8k8) + cp.async.
// All GEMM inputs pre-rounded to tf32 so the mainloop has zero cvt traffic.
// b=4, s=2048, h=1024, out=1024.
// ---------------------------------------------------------------------------

#define BATCH 4
#define SEQ   2048
#define HID   1024
#define OUTD  1024
#define ROWS  (BATCH * SEQ)          // 8192

// Scratch layout (floats):
//   Xr   : ROWS*HID                  (8M)
//   Wqr,Wkr,Wvr,Whr : HID*HID each   (4M)
//   Q,K,V,Ctx : ROWS*HID each        (32M)
//   S    : BATCH*SEQ*SEQ             (16M)
__device__ float g_scratch[63ull * 1024 * 1024];

// ----------------------------- PTX helpers --------------------------------
__device__ __forceinline__ void cp_async16(void* smem, const void* gmem) {
    uint32_t s = (uint32_t)__cvta_generic_to_shared(smem);
    asm volatile("cp.async.cg.shared.global [%0], [%1], 16;\n" :: "r"(s), "l"(gmem));
}
__device__ __forceinline__ void cp_commit() { asm volatile("cp.async.commit_group;\n"); }
__device__ __forceinline__ void cp_wait1()  { asm volatile("cp.async.wait_group 1;\n"); }
__device__ __forceinline__ void cp_wait0()  { asm volatile("cp.async.wait_group 0;\n"); }

__device__ __forceinline__ float round_tf32(float x) {
    uint32_t r;
    asm("cvt.rna.tf32.f32 %0, %1;\n" : "=r"(r) : "f"(x));
    return __uint_as_float(r);
}

__device__ __forceinline__ void mma_tf32(float* d, const uint32_t* a, const uint32_t* b) {
    asm volatile(
        "mma.sync.aligned.m16n8k8.row.col.f32.tf32.tf32.f32 "
        "{%0,%1,%2,%3}, {%4,%5,%6,%7}, {%8,%9}, {%0,%1,%2,%3};\n"
        : "+f"(d[0]), "+f"(d[1]), "+f"(d[2]), "+f"(d[3])
        : "r"(a[0]), "r"(a[1]), "r"(a[2]), "r"(a[3]), "r"(b[0]), "r"(b[1]));
}

// Tile geometry
#define BM 128
#define BN 128
#define BK 32
#define APAD 4     // row stride 36 floats -> fragment LDS conflict-free
#define BPAD 8     // row stride 136 floats -> fragment LDS conflict-free
#define ASTR (BK + APAD)     // 36
#define BSTR (BN + BPAD)     // 136

#define A_TILE_F (BM * ASTR)            // 4608 floats per buffer
#define BN_TILE_F (BK * BSTR)           // 4352 floats per buffer (NN layout)
#define BT_TILE_F (BM * ASTR)           // 4608 floats per buffer (NT layout)

// ===========================================================================
// Elementwise tf32 rounding: out[i] = tf32(in[i]), n % 1024 == 0.
// ===========================================================================
__global__ __launch_bounds__(256)
void round_tf32_kernel(const float* __restrict__ in, float* __restrict__ out,
                       long long n)
{
    long long i = ((long long)blockIdx.x * 256 + threadIdx.x) * 4;
    if (i >= n) return;
    float4 v = *(const float4*)(in + i);
    v.x = round_tf32(v.x);
    v.y = round_tf32(v.y);
    v.z = round_tf32(v.z);
    v.w = round_tf32(v.w);
    *(float4*)(out + i) = v;
}

// ===========================================================================
// NN: C[M,N] = (A[M,K] @ B[K,N] + bias) * oscale, optionally tf32-rounded.
// Inputs A,B must already be tf32-rounded. Batched via blockIdx.z.
// ===========================================================================
__global__ __launch_bounds__(256, 2)
void gemm_nn_tc(const float* __restrict__ A, const float* __restrict__ B,
                const float* __restrict__ bias, float* __restrict__ C,
                int M, int N, int K,
                long long sA, long long sB, long long sC,
                float oscale, int roundOut)
{
    A += (long long)blockIdx.z * sA;
    B += (long long)blockIdx.z * sB;
    C += (long long)blockIdx.z * sC;

    extern __shared__ float smem[];
    float* As = smem;                       // [2][BM][ASTR]
    float* Bs = smem + 2 * A_TILE_F;        // [2][BK][BSTR]

    const int tid  = threadIdx.x;
    const int lane = tid & 31;
    const int warp = tid >> 5;
    const int wm = warp >> 2;               // 0..1  -> 64-row slab
    const int wn = warp & 3;                // 0..3  -> 32-col slab
    const int g  = lane >> 2;               // 0..7
    const int t4 = lane & 3;                // 0..3

    const int m0 = blockIdx.y * BM;
    const int n0 = blockIdx.x * BN;

    const int lr = tid >> 3;                // 0..31
    const int lc = (tid & 7) * 4;           // 0,4,...,28

    const float* Ag = A + (long long)(m0 + lr) * K + lc;
    const float* Bg = B + (long long)lr * N + n0 + lc;

    float acc[4][4][4];
    #pragma unroll
    for (int i = 0; i < 4; ++i)
        #pragma unroll
        for (int j = 0; j < 4; ++j)
            #pragma unroll
            for (int q = 0; q < 4; ++q) acc[i][j][q] = 0.f;

    const int iters = K / BK;

    {
        float* ab = As;
        float* bb = Bs;
        #pragma unroll
        for (int p = 0; p < 4; ++p)
            cp_async16(&ab[(lr + p * 32) * ASTR + lc], Ag + (long long)p * 32 * K);
        #pragma unroll
        for (int p = 0; p < 4; ++p)
            cp_async16(&bb[lr * BSTR + lc + p * 32], Bg + p * 32);
        cp_commit();
    }

    for (int it = 0; it < iters; ++it) {
        const int buf = it & 1;
        if (it + 1 < iters) {
            const int k0n = (it + 1) * BK;
            float* ab = As + (buf ^ 1) * A_TILE_F;
            float* bb = Bs + (buf ^ 1) * BN_TILE_F;
            #pragma unroll
            for (int p = 0; p < 4; ++p)
                cp_async16(&ab[(lr + p * 32) * ASTR + lc],
                           Ag + (long long)p * 32 * K + k0n);
            #pragma unroll
            for (int p = 0; p < 4; ++p)
                cp_async16(&bb[lr * BSTR + lc + p * 32],
                           Bg + (long long)k0n * N + p * 32);
            cp_commit();
            cp_wait1();
        } else {
            cp_wait0();
        }
        __syncthreads();

        const float* ab = As + buf * A_TILE_F;
        const float* bb = Bs + buf * BN_TILE_F;

        #pragma unroll
        for (int kk = 0; kk < BK; kk += 8) {
            uint32_t af[4][4], bf[4][2];
            #pragma unroll
            for (int im = 0; im < 4; ++im) {
                const int m = wm * 64 + im * 16;
                af[im][0] = __float_as_uint(ab[(m + g)     * ASTR + kk + t4]);
                af[im][1] = __float_as_uint(ab[(m + g + 8) * ASTR + kk + t4]);
                af[im][2] = __float_as_uint(ab[(m + g)     * ASTR + kk + t4 + 4]);
                af[im][3] = __float_as_uint(ab[(m + g + 8) * ASTR + kk + t4 + 4]);
            }
            #pragma unroll
            for (int in = 0; in < 4; ++in) {
                const int n = wn * 32 + in * 8;
                bf[in][0] = __float_as_uint(bb[(kk + t4)     * BSTR + n + g]);
                bf[in][1] = __float_as_uint(bb[(kk + t4 + 4) * BSTR + n + g]);
            }
            #pragma unroll
            for (int im = 0; im < 4; ++im)
                #pragma unroll
                for (int in = 0; in < 4; ++in)
                    mma_tf32(acc[im][in], af[im], bf[in]);
        }
        __syncthreads();
    }

    #pragma unroll
    for (int im = 0; im < 4; ++im) {
        const int r0 = m0 + wm * 64 + im * 16 + g;
        #pragma unroll
        for (int in = 0; in < 4; ++in) {
            const int c = n0 + wn * 32 + in * 8 + 2 * t4;
            float b0 = 0.f, b1 = 0.f;
            if (bias) { b0 = bias[c]; b1 = bias[c + 1]; }
            float v0 = (acc[im][in][0] + b0) * oscale;
            float v1 = (acc[im][in][1] + b1) * oscale;
            float v2 = (acc[im][in][2] + b0) * oscale;
            float v3 = (acc[im][in][3] + b1) * oscale;
            if (roundOut) {
                v0 = round_tf32(v0); v1 = round_tf32(v1);
                v2 = round_tf32(v2); v3 = round_tf32(v3);
            }
            *(float2*)&C[(long long)r0 * N + c]       = make_float2(v0, v1);
            *(float2*)&C[(long long)(r0 + 8) * N + c] = make_float2(v2, v3);
        }
    }
}

// ===========================================================================
// NT: C[M,N] = A[M,K] @ B[N,K]^T, batched via blockIdx.z. Inputs pre-rounded.
// ===========================================================================
__global__ __launch_bounds__(256, 2)
void gemm_nt_tc(const float* __restrict__ A, const float* __restrict__ B,
                float* __restrict__ C,
                int M, int N, int K,
                long long sA, long long sB, long long sC)
{
    A += (long long)blockIdx.z * sA;
    B += (long long)blockIdx.z * sB;
    C += (long long)blockIdx.z * sC;

    extern __shared__ float smem[];
    float* As = smem;                       // [2][BM][ASTR]
    float* Bs = smem + 2 * A_TILE_F;        // [2][BN][ASTR]

    const int tid  = threadIdx.x;
    const int lane = tid & 31;
    const int warp = tid >> 5;
    const int wm = warp >> 2;
    const int wn = warp & 3;
    const int g  = lane >> 2;
    const int t4 = lane & 3;

    const int m0 = blockIdx.y * BM;
    const int n0 = blockIdx.x * BN;

    const int lr = tid >> 3;
    const int lc = (tid & 7) * 4;

    const float* Ag = A + (long long)(m0 + lr) * K + lc;
    const float* Bg = B + (long long)(n0 + lr) * K + lc;

    float acc[4][4][4];
    #pragma unroll
    for (int i = 0; i < 4; ++i)
        #pragma unroll
        for (int j = 0; j < 4; ++j)
            #pragma unroll
            for (int q = 0; q < 4; ++q) acc[i][j][q] = 0.f;

    const int iters = K / BK;

    {
        float* ab = As;
        float* bb = Bs;
        #pragma unroll
        for (int p = 0; p < 4; ++p)
            cp_async16(&ab[(lr + p * 32) * ASTR + lc], Ag + (long long)p * 32 * K);
        #pragma unroll
        for (int p = 0; p < 4; ++p)
            cp_async16(&bb[(lr + p * 32) * ASTR + lc], Bg + (long long)p * 32 * K);
        cp_commit();
    }

    for (int it = 0; it < iters; ++it) {
        const int buf = it & 1;
        if (it + 1 < iters) {
            const int k0n = (it + 1) * BK;
            float* ab = As + (buf ^ 1) * A_TILE_F;
            float* bb = Bs + (buf ^ 1) * BT_TILE_F;
            #pragma unroll
            for (int p = 0; p < 4; ++p)
                cp_async16(&ab[(lr + p * 32) * ASTR + lc],
                           Ag + (long long)p * 32 * K + k0n);
            #pragma unroll
            for (int p = 0; p < 4; ++p)
                cp_async16(&bb[(lr + p * 32) * ASTR + lc],
                           Bg + (long long)p * 32 * K + k0n);
            cp_commit();
            cp_wait1();
        } else {
            cp_wait0();
        }
        __syncthreads();

        const float* ab = As + buf * A_TILE_F;
        const float* bb = Bs + buf * BT_TILE_F;

        #pragma unroll
        for (int kk = 0; kk < BK; kk += 8) {
            uint32_t af[4][4], bf[4][2];
            #pragma unroll
            for (int im = 0; im < 4; ++im) {
                const int m = wm * 64 + im * 16;
                af[im][0] = __float_as_uint(ab[(m + g)     * ASTR + kk + t4]);
                af[im][1] = __float_as_uint(ab[(m + g + 8) * ASTR + kk + t4]);
                af[im][2] = __float_as_uint(ab[(m + g)     * ASTR + kk + t4 + 4]);
                af[im][3] = __float_as_uint(ab[(m + g + 8) * ASTR + kk + t4 + 4]);
            }
            #pragma unroll
            for (int in = 0; in < 4; ++in) {
                const int n = wn * 32 + in * 8;
                bf[in][0] = __float_as_uint(bb[(n + g) * ASTR + kk + t4]);
                bf[in][1] = __float_as_uint(bb[(n + g) * ASTR + kk + t4 + 4]);
            }
            #pragma unroll
            for (int im = 0; im < 4; ++im)
                #pragma unroll
                for (int in = 0; in < 4; ++in)
                    mma_tf32(acc[im][in], af[im], bf[in]);
        }
        __syncthreads();
    }

    #pragma unroll
    for (int im = 0; im < 4; ++im) {
        const int r0 = m0 + wm * 64 + im * 16 + g;
        #pragma unroll
        for (int in = 0; in < 4; ++in) {
            const int c = n0 + wn * 32 + in * 8 + 2 * t4;
            *(float2*)&C[(long long)r0 * N + c] =
                make_float2(acc[im][in][0], acc[im][in][1]);
            *(float2*)&C[(long long)(r0 + 8) * N + c] =
                make_float2(acc[im][in][2], acc[im][in][3]);
        }
    }
}

// ===========================================================================
// Row softmax, one block per row. Output tf32-rounded (feeds attn@V GEMM).
// ===========================================================================
__global__ __launch_bounds__(256)
void softmax_rows(float* __restrict__ S, int N)
{
    float* row = S + (long long)blockIdx.x * N;
    const int tid = threadIdx.x;
    const int lane = tid & 31;
    const int warp = tid >> 5;
    __shared__ float red[8];

    // N = 2048 -> 2 float4 per thread
    float4 v0 = *(const float4*)(row + tid * 4);
    float4 v1 = *(const float4*)(row + 1024 + tid * 4);

    float vmax = fmaxf(fmaxf(fmaxf(v0.x, v0.y), fmaxf(v0.z, v0.w)),
                       fmaxf(fmaxf(v1.x, v1.y), fmaxf(v1.z, v1.w)));
    #pragma unroll
    for (int s = 16; s > 0; s >>= 1)
        vmax = fmaxf(vmax, __shfl_xor_sync(0xffffffffu, vmax, s));
    if (lane == 0) red[warp] = vmax;
    __syncthreads();
    float m = red[0];
    #pragma unroll
    for (int w = 1; w < 8; ++w) m = fmaxf(m, red[w]);

    v0.x = __expf(v0.x - m); v0.y = __expf(v0.y - m);
    v0.z = __expf(v0.z - m); v0.w = __expf(v0.w - m);
    v1.x = __expf(v1.x - m); v1.y = __expf(v1.y - m);
    v1.z = __expf(v1.z - m); v1.w = __expf(v1.w - m);

    float sum = v0.x + v0.y + v0.z + v0.w + v1.x + v1.y + v1.z + v1.w;
    #pragma unroll
    for (int s = 16; s > 0; s >>= 1)
        sum += __shfl_xor_sync(0xffffffffu, sum, s);
    __syncthreads();
    if (lane == 0) red[warp] = sum;
    __syncthreads();
    float tot = 0.f;
    #pragma unroll
    for (int w = 0; w < 8; ++w) tot += red[w];
    const float inv = 1.f / tot;

    v0.x = round_tf32(v0.x * inv); v0.y = round_tf32(v0.y * inv);
    v0.z = round_tf32(v0.z * inv); v0.w = round_tf32(v0.w * inv);
    v1.x = round_tf32(v1.x * inv); v1.y = round_tf32(v1.y * inv);
    v1.z = round_tf32(v1.z * inv); v1.w = round_tf32(v1.w * inv);

    *(float4*)(row + tid * 4) = v0;
    *(float4*)(row + 1024 + tid * 4) = v1;
}

// ===========================================================================
extern "C" void kernel_launch(void* const* d_in, const int* in_sizes, int n_in,
                              void* d_out, int out_size)
{
    const float* X  = (const float*)d_in[0];
    const float* Wq = (const float*)d_in[1];
    const float* bq = (const float*)d_in[2];
    const float* Wk = (const float*)d_in[3];
    const float* bk = (const float*)d_in[4];
    const float* Wv = (const float*)d_in[5];
    const float* bv = (const float*)d_in[6];
    const float* Wh = (const float*)d_in[7];
    const float* bh = (const float*)d_in[8];
    float* out = (float*)d_out;

    float* base = nullptr;
    cudaGetSymbolAddress((void**)&base, g_scratch);
    const long long XHF = (long long)ROWS * HID;   // 8M
    const long long WF  = (long long)HID * HID;    // 1M
    float* Xr  = base;
    float* Wqr = Xr + XHF;
    float* Wkr = Wqr + WF;
    float* Wvr = Wkr + WF;
    float* Whr = Wvr + WF;
    float* Q   = Whr + WF;
    float* K   = Q + XHF;
    float* V   = K + XHF;
    float* Ctx = V + XHF;
    float* S   = Ctx + XHF;

    const float scale = 1.0f / 32.0f;  // 1/sqrt(1024), folded into Q

    const int smem_nn = (2 * A_TILE_F + 2 * BN_TILE_F) * (int)sizeof(float);  // 71680
    const int smem_nt = (2 * A_TILE_F + 2 * BT_TILE_F) * (int)sizeof(float);  // 73728

    cudaFuncSetAttribute(gemm_nn_tc, cudaFuncAttributeMaxDynamicSharedMemorySize, smem_nn);
    cudaFuncSetAttribute(gemm_nt_tc, cudaFuncAttributeMaxDynamicSharedMemorySize, smem_nt);

    // Pre-round GEMM inputs to tf32.
    round_tf32_kernel<<<(unsigned)(XHF / 4 / 256), 256>>>(X,  Xr,  XHF);
    round_tf32_kernel<<<(unsigned)(WF  / 4 / 256), 256>>>(Wq, Wqr, WF);
    round_tf32_kernel<<<(unsigned)(WF  / 4 / 256), 256>>>(Wk, Wkr, WF);
    round_tf32_kernel<<<(unsigned)(WF  / 4 / 256), 256>>>(Wv, Wvr, WF);
    round_tf32_kernel<<<(unsigned)(WF  / 4 / 256), 256>>>(Wh, Whr, WF);

    // Q/K/V projections (round outputs; Q pre-scaled by 1/32)
    {
        dim3 grid(HID / BN, ROWS / BM, 1);
        gemm_nn_tc<<<grid, 256, smem_nn>>>(Xr, Wqr, bq, Q, ROWS, HID, HID, 0, 0, 0, scale, 1);
        gemm_nn_tc<<<grid, 256, smem_nn>>>(Xr, Wkr, bk, K, ROWS, HID, HID, 0, 0, 0, 1.0f, 1);
        gemm_nn_tc<<<grid, 256, smem_nn>>>(Xr, Wvr, bv, V, ROWS, HID, HID, 0, 0, 0, 1.0f, 1);
    }

    // scores = Q @ K^T (scale already folded into Q)
    {
        dim3 grid(SEQ / BN, SEQ / BM, BATCH);
        gemm_nt_tc<<<grid, 256, smem_nt>>>(Q, K, S, SEQ, SEQ, HID,
                                           (long long)SEQ * HID,
                                           (long long)SEQ * HID,
                                           (long long)SEQ * SEQ);
    }

    softmax_rows<<<BATCH * SEQ, 256>>>(S, SEQ);

    // context = attn @ V (round output)
    {
        dim3 grid(HID / BN, SEQ / BM, BATCH);
        gemm_nn_tc<<<grid, 256, smem_nn>>>(S, V, nullptr, Ctx, SEQ, HID, SEQ,
                                           (long long)SEQ * SEQ,
                                           (long long)SEQ * HID,
                                           (long long)SEQ * HID, 1.0f, 1);
    }

    // y = context @ Wh + bh (exact fp32 output)
    {
        dim3 grid(OUTD / BN, ROWS / BM, 1);
        gemm_nn_tc<<<grid, 256, smem_nn>>>(Ctx, Whr, bh, out, ROWS, OUTD, HID, 0, 0, 0, 1.0f, 0);
    }
}